// round 9
// baseline (speedup 1.0000x reference)
#include <cuda_runtime.h>

// AllReduce_77335181131889 — TP=4 sum + bias + residual + RMSNorm, fp32.
// R9: persistent pipelined kernel. grid = #SMs, 1 CTA/SM (128-reg budget),
// each CTA grid-strides over rows. Next row's 10 streaming float4 loads are
// issued BEFORE the current row's reduction barriers, hiding the tail.
// bias/norm_weight are row-invariant per thread -> loaded once in prologue.

#define T_DIM 8192
#define H_DIM 4096
#define H4    (H_DIM / 4)      // 1024 float4 per row
#define NTHREADS 512
#define VPT 2                  // float4 vectors per thread

__global__ __launch_bounds__(NTHREADS, 1)
void fused_ar_rmsnorm_persist(const float4* __restrict__ x,      // [4*T*H4]
                              const float4* __restrict__ res,    // [T*H4]
                              const float4* __restrict__ bias,   // [H4]
                              const float4* __restrict__ w,      // [H4]
                              float4* __restrict__ norm_out,     // [T*H4]
                              float4* __restrict__ inter_out)    // [T*H4]
{
    const long rs = (long)T_DIM * H4;   // rank stride in float4
    const int  stride = gridDim.x;

    // Row-invariant per-thread data: load once.
    float4 bi[VPT], wt[VPT];
    #pragma unroll
    for (int i = 0; i < VPT; i++) {
        const int col = threadIdx.x + i * NTHREADS;
        bi[i] = bias[col];
        wt[i] = w[col];
    }

    __shared__ float warp_ss[NTHREADS / 32];
    __shared__ float scale_sh;
    const int wid = threadIdx.x >> 5;
    const int lid = threadIdx.x & 31;

    // Raw streaming buffers for the row currently in flight.
    float4 ra[VPT], rb[VPT], rc[VPT], rd[VPT], rr[VPT];

    int row = blockIdx.x;

    // Prologue: issue loads for the first row.
    if (row < T_DIM) {
        const long ro = (long)row * H4;
        #pragma unroll
        for (int i = 0; i < VPT; i++) {
            const long p = ro + threadIdx.x + i * NTHREADS;
            ra[i] = x[p];
            rb[i] = x[rs + p];
            rc[i] = x[2 * rs + p];
            rd[i] = x[3 * rs + p];
            rr[i] = res[p];
        }
    }

    while (row < T_DIM) {
        const long rowOff = (long)row * H4;
        const int  rnext  = row + stride;

        // Consume raw loads -> intermediate + sum of squares; stream inter out.
        float4 inter[VPT];
        float ss = 0.0f;
        #pragma unroll
        for (int i = 0; i < VPT; i++) {
            const long p = rowOff + threadIdx.x + i * NTHREADS;
            float4 v;
            v.x = ((ra[i].x + rb[i].x) + (rc[i].x + rd[i].x)) + (bi[i].x + rr[i].x);
            v.y = ((ra[i].y + rb[i].y) + (rc[i].y + rd[i].y)) + (bi[i].y + rr[i].y);
            v.z = ((ra[i].z + rb[i].z) + (rc[i].z + rd[i].z)) + (bi[i].z + rr[i].z);
            v.w = ((ra[i].w + rb[i].w) + (rc[i].w + rd[i].w)) + (bi[i].w + rr[i].w);

            ss = fmaf(v.x, v.x, ss);
            ss = fmaf(v.y, v.y, ss);
            ss = fmaf(v.z, v.z, ss);
            ss = fmaf(v.w, v.w, ss);

            inter[i] = v;
            inter_out[p] = v;
        }

        // Prefetch next row BEFORE the reduction barriers: these loads keep
        // DRAM busy while this row's tail (shuffles/barriers/rsqrt) runs.
        if (rnext < T_DIM) {
            const long ro = (long)rnext * H4;
            #pragma unroll
            for (int i = 0; i < VPT; i++) {
                const long p = ro + threadIdx.x + i * NTHREADS;
                ra[i] = x[p];
                rb[i] = x[rs + p];
                rc[i] = x[2 * rs + p];
                rd[i] = x[3 * rs + p];
                rr[i] = res[p];
            }
        }

        // Block reduction of sum of squares (R2 scheme — measured best).
        #pragma unroll
        for (int off = 16; off > 0; off >>= 1)
            ss += __shfl_xor_sync(0xFFFFFFFFu, ss, off);
        if (lid == 0) warp_ss[wid] = ss;
        __syncthreads();
        if (wid == 0) {
            float s = (lid < NTHREADS / 32) ? warp_ss[lid] : 0.0f;
            #pragma unroll
            for (int off = 8; off > 0; off >>= 1)
                s += __shfl_xor_sync(0xFFFFFFFFu, s, off);
            if (lid == 0)
                scale_sh = rsqrtf(s * (1.0f / (float)H_DIM) + 1e-6f);
        }
        __syncthreads();
        const float scale = scale_sh;
        __syncthreads();   // protect scale_sh before next iteration overwrites

        // Tail: pure register math + stores (weights resident since prologue).
        #pragma unroll
        for (int i = 0; i < VPT; i++) {
            const long p = rowOff + threadIdx.x + i * NTHREADS;
            float4 v = inter[i];
            float4 o;
            o.x = v.x * scale * wt[i].x;
            o.y = v.y * scale * wt[i].y;
            o.z = v.z * scale * wt[i].z;
            o.w = v.w * scale * wt[i].w;
            norm_out[p] = o;
        }

        row = rnext;
    }
}

extern "C" void kernel_launch(void* const* d_in, const int* in_sizes, int n_in,
                              void* d_out, int out_size)
{
    const float4* x    = (const float4*)d_in[0];   // x_ranks [4,T,H]
    const float4* res  = (const float4*)d_in[1];   // residual [T,H]
    const float4* bias = (const float4*)d_in[2];   // bias [H]
    const float4* w    = (const float4*)d_in[3];   // norm_weight [H]

    float* out = (float*)d_out;
    float4* norm_out  = (float4*)out;                              // first T*H
    float4* inter_out = (float4*)(out + (long)T_DIM * H_DIM);      // second T*H

    int dev = 0, nsm = 148;
    cudaGetDevice(&dev);
    cudaDeviceGetAttribute(&nsm, cudaDevAttrMultiProcessorCount, dev);

    fused_ar_rmsnorm_persist<<<nsm, NTHREADS>>>(x, res, bias, w, norm_out, inter_out);
}

// round 12
// speedup vs baseline: 1.0120x; 1.0120x over previous
#include <cuda_runtime.h>

// AllReduce_77335181131889 — TP=4 sum + bias + residual + RMSNorm, fp32.
// R10: R8 body (measured best, 64 regs) made persistent: grid = 2*SMs,
// 2 CTAs/SM (two independent barrier domains cover each other's tails),
// grid-stride over rows. bias/norm_weight loaded once per CTA instead of
// per row. No explicit prefetch (R9 showed it costs more regs than it pays).

#define T_DIM 8192
#define H_DIM 4096
#define H4    (H_DIM / 4)      // 1024 float4 per row
#define NTHREADS 512
#define VPT 2                  // float4 vectors per thread

__global__ __launch_bounds__(NTHREADS, 2)
void fused_ar_rmsnorm_persist2(const float4* __restrict__ x,      // [4*T*H4]
                               const float4* __restrict__ res,    // [T*H4]
                               const float4* __restrict__ bias,   // [H4]
                               const float4* __restrict__ w,      // [H4]
                               float4* __restrict__ norm_out,     // [T*H4]
                               float4* __restrict__ inter_out)    // [T*H4]
{
    const long rs = (long)T_DIM * H4;   // rank stride in float4
    const int  stride = gridDim.x;

    // Row-invariant per-thread data: load once per CTA.
    float4 bi[VPT], wt[VPT];
    #pragma unroll
    for (int i = 0; i < VPT; i++) {
        const int col = threadIdx.x + i * NTHREADS;
        bi[i] = bias[col];
        wt[i] = w[col];
    }

    __shared__ float warp_ss[NTHREADS / 32];
    __shared__ float scale_sh;
    const int wid = threadIdx.x >> 5;
    const int lid = threadIdx.x & 31;

    for (int row = blockIdx.x; row < T_DIM; row += stride) {
        const long rowOff = (long)row * H4;

        // Front-batched streaming loads: 4 ranks + residual, x2 vectors.
        float4 inter[VPT];
        float ss = 0.0f;
        #pragma unroll
        for (int i = 0; i < VPT; i++) {
            const long p = rowOff + threadIdx.x + i * NTHREADS;
            float4 a = x[p];
            float4 b = x[rs + p];
            float4 c = x[2 * rs + p];
            float4 d = x[3 * rs + p];
            float4 r = res[p];

            float4 v;
            v.x = ((a.x + b.x) + (c.x + d.x)) + (bi[i].x + r.x);
            v.y = ((a.y + b.y) + (c.y + d.y)) + (bi[i].y + r.y);
            v.z = ((a.z + b.z) + (c.z + d.z)) + (bi[i].z + r.z);
            v.w = ((a.w + b.w) + (c.w + d.w)) + (bi[i].w + r.w);

            ss = fmaf(v.x, v.x, ss);
            ss = fmaf(v.y, v.y, ss);
            ss = fmaf(v.z, v.z, ss);
            ss = fmaf(v.w, v.w, ss);

            inter[i] = v;
            inter_out[p] = v;   // stream intermediate out immediately
        }

        // Block reduction of sum of squares (R2/R8 scheme — measured best).
        #pragma unroll
        for (int off = 16; off > 0; off >>= 1)
            ss += __shfl_xor_sync(0xFFFFFFFFu, ss, off);
        if (lid == 0) warp_ss[wid] = ss;
        __syncthreads();
        if (wid == 0) {
            float s = (lid < NTHREADS / 32) ? warp_ss[lid] : 0.0f;
            #pragma unroll
            for (int off = 8; off > 0; off >>= 1)
                s += __shfl_xor_sync(0xFFFFFFFFu, s, off);
            if (lid == 0)
                scale_sh = rsqrtf(s * (1.0f / (float)H_DIM) + 1e-6f);
        }
        __syncthreads();
        const float scale = scale_sh;

        // Tail: pure register math + stores (weights resident).
        #pragma unroll
        for (int i = 0; i < VPT; i++) {
            const long p = rowOff + threadIdx.x + i * NTHREADS;
            float4 v = inter[i];
            float4 o;
            o.x = v.x * scale * wt[i].x;
            o.y = v.y * scale * wt[i].y;
            o.z = v.z * scale * wt[i].z;
            o.w = v.w * scale * wt[i].w;
            norm_out[p] = o;
        }

        // Protect scale_sh/warp_ss against next iteration's overwrite.
        __syncthreads();
    }
}

extern "C" void kernel_launch(void* const* d_in, const int* in_sizes, int n_in,
                              void* d_out, int out_size)
{
    const float4* x    = (const float4*)d_in[0];   // x_ranks [4,T,H]
    const float4* res  = (const float4*)d_in[1];   // residual [T,H]
    const float4* bias = (const float4*)d_in[2];   // bias [H]
    const float4* w    = (const float4*)d_in[3];   // norm_weight [H]

    float* out = (float*)d_out;
    float4* norm_out  = (float4*)out;                              // first T*H
    float4* inter_out = (float4*)(out + (long)T_DIM * H_DIM);      // second T*H

    int dev = 0, nsm = 148;
    cudaGetDevice(&dev);
    cudaDeviceGetAttribute(&nsm, cudaDevAttrMultiProcessorCount, dev);

    fused_ar_rmsnorm_persist2<<<2 * nsm, NTHREADS>>>(x, res, bias, w, norm_out, inter_out);
}

// round 13
// speedup vs baseline: 1.0280x; 1.0158x over previous
#include <cuda_runtime.h>

// AllReduce_77335181131889 — TP=4 sum + bias + residual + RMSNorm, fp32.
// R13: R8 body (measured best: one CTA per row, 512 thr, 2 CTA/SM, hoisted
// weight loads) with a single-barrier symmetric reduction finish:
// warp partials -> one __syncthreads -> every warp LDS(16 partials over
// lanes 0-15) + 5-step xor-shuffle -> block sum in every lane -> local rsqrt.
// Removes the second barrier, warp-0 serialization, and scale broadcast.

#define T_DIM 8192
#define H_DIM 4096
#define H4    (H_DIM / 4)      // 1024 float4 per row
#define NTHREADS 512
#define VPT 2                  // float4 vectors per thread
#define NWARPS (NTHREADS / 32) // 16

__global__ __launch_bounds__(NTHREADS, 2)
void fused_ar_rmsnorm_kernel(const float4* __restrict__ x,      // [4*T*H4]
                             const float4* __restrict__ res,    // [T*H4]
                             const float4* __restrict__ bias,   // [H4]
                             const float4* __restrict__ w,      // [H4]
                             float4* __restrict__ norm_out,     // [T*H4]
                             float4* __restrict__ inter_out)    // [T*H4]
{
    const int row = blockIdx.x;
    const long rowOff = (long)row * H4;
    const long rs = (long)T_DIM * H4;   // rank stride in float4

    float4 inter[VPT];
    float4 wt[VPT];
    float ss = 0.0f;

    // Front-batched loads: 4 ranks + residual + bias + weight per vector.
    #pragma unroll
    for (int i = 0; i < VPT; i++) {
        const int col = threadIdx.x + i * NTHREADS;       // 0..1023
        const long p = rowOff + col;
        float4 a  = x[p];
        float4 b  = x[rs + p];
        float4 c  = x[2 * rs + p];
        float4 d  = x[3 * rs + p];
        float4 r  = res[p];
        float4 bi = bias[col];
        wt[i]     = w[col];          // hoisted: hidden under streaming reads

        float4 v;
        v.x = ((a.x + b.x) + (c.x + d.x)) + (bi.x + r.x);
        v.y = ((a.y + b.y) + (c.y + d.y)) + (bi.y + r.y);
        v.z = ((a.z + b.z) + (c.z + d.z)) + (bi.z + r.z);
        v.w = ((a.w + b.w) + (c.w + d.w)) + (bi.w + r.w);

        ss = fmaf(v.x, v.x, ss);
        ss = fmaf(v.y, v.y, ss);
        ss = fmaf(v.z, v.z, ss);
        ss = fmaf(v.w, v.w, ss);

        inter[i] = v;
        inter_out[p] = v;   // stream intermediate out immediately
    }

    // Stage 1: warp-level reduction of sum of squares.
    #pragma unroll
    for (int off = 16; off > 0; off >>= 1)
        ss += __shfl_xor_sync(0xFFFFFFFFu, ss, off);

    __shared__ float warp_ss[NWARPS];
    const int wid = threadIdx.x >> 5;
    const int lid = threadIdx.x & 31;
    if (lid == 0) warp_ss[wid] = ss;
    __syncthreads();

    // Stage 2 (single barrier): every warp reduces the 16 partials itself.
    // Lanes 0-15 load distinct partials (conflict-free), others contribute 0;
    // full 5-step xor reduce leaves the block sum in every lane.
    float s = (lid < NWARPS) ? warp_ss[lid] : 0.0f;
    #pragma unroll
    for (int off = 16; off > 0; off >>= 1)
        s += __shfl_xor_sync(0xFFFFFFFFu, s, off);
    const float scale = rsqrtf(s * (1.0f / (float)H_DIM) + 1e-6f);

    // Tail: pure register math + stores (weights already resident).
    #pragma unroll
    for (int i = 0; i < VPT; i++) {
        const int col = threadIdx.x + i * NTHREADS;
        const long p = rowOff + col;
        float4 v = inter[i];
        float4 o;
        o.x = v.x * scale * wt[i].x;
        o.y = v.y * scale * wt[i].y;
        o.z = v.z * scale * wt[i].z;
        o.w = v.w * scale * wt[i].w;
        norm_out[p] = o;
    }
}

extern "C" void kernel_launch(void* const* d_in, const int* in_sizes, int n_in,
                              void* d_out, int out_size)
{
    const float4* x    = (const float4*)d_in[0];   // x_ranks [4,T,H]
    const float4* res  = (const float4*)d_in[1];   // residual [T,H]
    const float4* bias = (const float4*)d_in[2];   // bias [H]
    const float4* w    = (const float4*)d_in[3];   // norm_weight [H]

    float* out = (float*)d_out;
    float4* norm_out  = (float4*)out;                              // first T*H
    float4* inter_out = (float4*)(out + (long)T_DIM * H_DIM);      // second T*H

    fused_ar_rmsnorm_kernel<<<T_DIM, NTHREADS>>>(x, res, bias, w, norm_out, inter_out);
}